// round 2
// baseline (speedup 1.0000x reference)
#include <cuda_runtime.h>

#define NQ 12
#define NGATES 72      // NL * NQ
#define DIM 4096       // 2^NQ
#define DIN 512
#define THREADS 256

__global__ __launch_bounds__(THREADS) void dqc_kernel(
    const float* __restrict__ x,
    const float* __restrict__ pre_w,
    const float* __restrict__ pre_b,
    const float* __restrict__ weights,
    const float* __restrict__ post_w,
    const float* __restrict__ post_b,
    float* __restrict__ out)
{
    __shared__ float st[DIM];
    __shared__ float lo[64], hi[64];
    __shared__ float vv0[NQ], vv1[NQ];
    __shared__ float gc[NGATES], gs[NGATES];
    __shared__ unsigned short gmask[NGATES], gsel[NGATES], msel[NQ];
    __shared__ float wsum[8][NQ];
    __shared__ float red[8];
    __shared__ float postw_s[NQ];

    const int tid  = threadIdx.x;
    const int b    = blockIdx.x;
    const int lane = tid & 31;
    const int warp = tid >> 5;

    // ---------------- pre-layer: 12 dot products of length 512 ----------------
    float2 xv = ((const float2*)(x + (size_t)b * DIN))[tid];
    float acc[NQ];
#pragma unroll
    for (int w = 0; w < NQ; w++) {
        float2 pv = ((const float2*)(pre_w + w * DIN))[tid];
        acc[w] = xv.x * pv.x + xv.y * pv.y;
    }
#pragma unroll
    for (int o = 16; o; o >>= 1)
#pragma unroll
        for (int w = 0; w < NQ; w++)
            acc[w] += __shfl_xor_sync(0xffffffffu, acc[w], o);
    if (lane == 0) {
#pragma unroll
        for (int w = 0; w < NQ; w++) wsum[warp][w] = acc[w];
    }
    __syncthreads();

    // ---------------- finalize angles, gate trig, GF(2) circuit structure ------
    if (tid < NQ) {
        float s = pre_b[tid];
#pragma unroll
        for (int k = 0; k < 8; k++) s += wsum[k][tid];
        // angle = pre * pi/2 ; half-angle = pre * pi/4
        float h = s * 0.78539816339744830962f;
        float c, sn;
        sincosf(h, &sn, &c);
        const float is2 = 0.70710678118654752440f;
        vv0[tid] = (c - sn) * is2;   // |0> component
        vv1[tid] = (c + sn) * is2;   // |1> component
        postw_s[tid] = post_w[tid];
    }
    if (tid >= 32 && tid < 32 + NGATES) {
        int g = tid - 32;
        float h = 0.5f * weights[g];   // weights is [6][12] row-major = gate order
        float c, sn;
        sincosf(h, &sn, &c);
        gc[g] = c; gs[g] = sn;
    }
    if (tid == 127) {
        // CNOT chain (w -> w+1, w=0..10) acts on basis index bits as y = A x,
        // A = lower-triangular all-ones (prefix-xor). Track A^l and A^-l so the
        // permutations are never applied to the state:
        //   RY on logical qubit w at layer l: pair (i, i^mask), mask = col_w(A^-l),
        //   role bit = parity(i & sel), sel = row_w(A^l).
        unsigned Ap[NQ], Aip[NQ];
#pragma unroll
        for (int i = 0; i < NQ; i++) { Ap[i] = 1u << i; Aip[i] = 1u << i; }
        for (int l = 0; l < 6; l++) {
            for (int w = 0; w < NQ; w++) {
                gsel[l * NQ + w] = (unsigned short)Ap[w];
                unsigned m = 0;
                for (int i = 0; i < NQ; i++) m |= ((Aip[i] >> w) & 1u) << i;
                gmask[l * NQ + w] = (unsigned short)m;
            }
            // Ap <- A * Ap  (rows become prefix-xor of rows)
            unsigned a = 0;
            for (int i = 0; i < NQ; i++) { a ^= Ap[i]; Ap[i] = a; }
            // Aip <- A^-1 * Aip  (row[i] ^= row[i-1], descending)
            for (int i = NQ - 1; i >= 1; i--) Aip[i] ^= Aip[i - 1];
        }
        for (int w = 0; w < NQ; w++) msel[w] = (unsigned short)Ap[w]; // rows of A^6
    }
    __syncthreads();

    // ---------------- product-state init: split 6+6 qubits ----------------
    if (tid < 128) {
        int base = (tid < 64) ? 0 : 6;
        int j = tid & 63;
        float p = 1.0f;
#pragma unroll
        for (int k = 0; k < 6; k++) {
            p *= ((j >> k) & 1) ? vv1[base + k] : vv0[base + k];
        }
        if (tid < 64) lo[j] = p; else hi[j] = p;
    }
    __syncthreads();
#pragma unroll
    for (int k = 0; k < DIM / THREADS; k++) {
        int i = tid + k * THREADS;
        st[i] = lo[i & 63] * hi[i >> 6];
    }
    __syncthreads();

    // ---------------- 72 RY sweeps (CNOTs folded into mask/sel) ----------------
    for (int g = 0; g < NGATES; g++) {
        float c = gc[g], s = gs[g];
        int mask = gmask[g], sel = gsel[g];
        int lb = mask & (-mask);
        int lm = lb - 1;
#pragma unroll
        for (int k = 0; k < 8; k++) {
            int r = tid + k * THREADS;            // 2048 pairs
            int i = ((r & ~lm) << 1) | (r & lm);  // insert 0 at lowest mask bit
            int p = i ^ mask;
            float a0 = st[i];
            float a1 = st[p];
            float ss = (__popc(i & sel) & 1) ? -s : s;
            st[i] = c * a0 - ss * a1;
            st[p] = ss * a0 + c * a1;
        }
        __syncthreads();
    }

    // ---------------- measurement fused with post layer ----------------
    unsigned ms[NQ];
    float pwv[NQ];
#pragma unroll
    for (int w = 0; w < NQ; w++) { ms[w] = msel[w]; pwv[w] = postw_s[w]; }

    float z = 0.0f;
#pragma unroll
    for (int k = 0; k < DIM / THREADS; k++) {
        int i = tid + k * THREADS;
        float a = st[i];
        float pr = a * a;
        float cf = 0.0f;
#pragma unroll
        for (int w = 0; w < NQ; w++)
            cf += (__popc(i & (int)ms[w]) & 1) ? -pwv[w] : pwv[w];
        z += pr * cf;
    }
#pragma unroll
    for (int o = 16; o; o >>= 1) z += __shfl_xor_sync(0xffffffffu, z, o);
    if (lane == 0) red[warp] = z;
    __syncthreads();
    if (tid == 0) {
        float t = post_b[0];
#pragma unroll
        for (int k = 0; k < 8; k++) t += red[k];
        out[b] = t;
    }
}

extern "C" void kernel_launch(void* const* d_in, const int* in_sizes, int n_in,
                              void* d_out, int out_size) {
    const float* x      = (const float*)d_in[0];
    const float* pre_w  = (const float*)d_in[1];
    const float* pre_b  = (const float*)d_in[2];
    const float* weights= (const float*)d_in[3];
    const float* post_w = (const float*)d_in[4];
    const float* post_b = (const float*)d_in[5];
    float* out = (float*)d_out;

    int batch = in_sizes[0] / DIN;   // 8192
    dqc_kernel<<<batch, THREADS>>>(x, pre_w, pre_b, weights, post_w, post_b, out);
}

// round 6
// speedup vs baseline: 3.0380x; 3.0380x over previous
#include <cuda_runtime.h>

#define NQ 12
#define NL 6
#define NG 72          // NL*NQ
#define DIM 4096
#define DIN 512
#define THREADS 256
#define KREG 16        // DIM / THREADS, state amps per thread

// ---------------------------------------------------------------------------
// Compile-time circuit structure.
// CNOT chain (w -> w+1) acts on basis indices as y = A x over GF(2), with A =
// lower-triangular all-ones (prefix-xor). We never permute the state; each RY
// at layer l on logical qubit w becomes a butterfly pairing (i, i^mask) with
//   mask = column w of A^-l,  role bit t(i) = parity(i & sel), sel = row w of A^l.
// Gate update: new(i) = c*old(i) + sg(i)*s*old(i^mask), sg(i) = +1 iff t(i)=1.
// Measurement <Z_w> uses sel = row w of A^6.
// ---------------------------------------------------------------------------
struct Circ {
    unsigned mask[NG];
    unsigned sel[NG];
    unsigned msel[NQ];
};

__host__ __device__ constexpr Circ make_circ() {
    Circ c{};
    unsigned Ap[NQ] = {}, Aip[NQ] = {};
    for (int i = 0; i < NQ; i++) { Ap[i] = 1u << i; Aip[i] = 1u << i; }
    for (int l = 0; l < NL; l++) {
        for (int w = 0; w < NQ; w++) {
            c.sel[l * NQ + w] = Ap[w];
            unsigned m = 0;
            for (int i = 0; i < NQ; i++) m |= ((Aip[i] >> w) & 1u) << i;
            c.mask[l * NQ + w] = m;
        }
        unsigned a = 0;
        for (int i = 0; i < NQ; i++) { a ^= Ap[i]; Ap[i] = a; }
        for (int i = NQ - 1; i >= 1; i--) Aip[i] ^= Aip[i - 1];
    }
    for (int w = 0; w < NQ; w++) c.msel[w] = Ap[w];
    return c;
}
constexpr Circ CC = make_circ();

__host__ __device__ constexpr int popc_ct(unsigned x) {
    int n = 0; while (x) { n += x & 1u; x >>= 1; } return n;
}
__host__ __device__ constexpr unsigned topbit(unsigned x) {
    unsigned r = 0;
    for (int b = 31; b >= 0; b--) if ((x >> b) & 1u) { r = 1u << b; break; }
    return r;
}
// sanity: every RY pair flips its role bit
constexpr bool check_circ() {
    for (int g = 0; g < NG; g++)
        if ((popc_ct(CC.mask[g] & CC.sel[g]) & 1) != 1) return false;
    return true;
}
static_assert(check_circ(), "mask.sel parity must be odd");

// number of shared-class gates before G (for ping-pong phase)
__host__ __device__ constexpr int shared_before(int G) {
    constexpr Circ c = make_circ();
    int n = 0;
    for (int g = 0; g < G; g++) if ((c.mask[g] & 7u) != 0) n++;
    return n;
}

// ---------------------------------------------------------------------------
// Kernel. Physical index layout: i = (k<<8) | (lane<<3) | warp
//   qubits 0..2  -> warp bits   (tid>>5)
//   qubits 3..7  -> lane bits   (tid&31)
//   qubits 8..11 -> register k  (per-thread)
// Shared publish layout (conflict-free): smem[k*256 + tid].
// ---------------------------------------------------------------------------

struct SmemT {
    float buf[2][DIM];     // ping-pong for cross-warp gates (32 KB)
    float gc[NG], gs[NG];
    float vv0[NQ], vv1[NQ];
    float wsum[8][NQ];
    float postw[NQ];
    float red[8];
};

template<int G>
__device__ __forceinline__ void apply_gate(float a[KREG], SmemT* sm, int tid, int tl8) {
    constexpr Circ CCk = make_circ();
    constexpr unsigned m   = CCk.mask[G];
    constexpr unsigned sl  = CCk.sel[G];
    constexpr unsigned mk  = m >> 8;          // register-bit part of mask
    constexpr unsigned ml  = (m >> 3) & 31u;  // lane-bit part
    constexpr unsigned mw  = m & 7u;          // warp-bit part
    constexpr unsigned slk = sl >> 8;         // register-bit part of sel
    constexpr unsigned slt = sl & 255u;       // thread-part of sel (bits 0..7 of i)

    const float c = sm->gc[G];
    const float s = sm->gs[G];
    // runtime half of the sign: parity of thread-part of i under sel
    const int pt = __popc((unsigned)tl8 & slt) & 1;
    const float sp = pt ? s : -s;
    // full sign for element with register-part k:  fs(k) = parity(k&slk) ? -sp : +sp

    if constexpr (mw == 0 && ml == 0) {
        // ---- register-local butterfly ----
        constexpr unsigned hb = topbit(mk);
#pragma unroll
        for (int k0 = 0; k0 < KREG; k0++) {
            if ((k0 & (int)hb) == 0) {
                const int k1 = k0 ^ (int)mk;
                const float fs0 = ((popc_ct((unsigned)k0 & slk) & 1) ? -sp : sp);
                const float fs1 = ((popc_ct((unsigned)k1 & slk) & 1) ? -sp : sp);
                const float n0 = fmaf(fs0, a[k1], c * a[k0]);
                const float n1 = fmaf(fs1, a[k0], c * a[k1]);
                a[k0] = n0; a[k1] = n1;
            }
        }
    } else if constexpr (mw == 0) {
        // ---- shuffle butterfly (lane exchange, compile-time delta) ----
        if constexpr (mk == 0) {
#pragma unroll
            for (int k = 0; k < KREG; k++) {
                const float v = __shfl_xor_sync(0xffffffffu, a[k], (int)ml);
                const float fs = ((popc_ct((unsigned)k & slk) & 1) ? -sp : sp);
                a[k] = fmaf(fs, v, c * a[k]);
            }
        } else {
            constexpr unsigned hb = topbit(mk);
#pragma unroll
            for (int k0 = 0; k0 < KREG; k0++) {
                if ((k0 & (int)hb) == 0) {
                    const int k1 = k0 ^ (int)mk;
                    const float v1 = __shfl_xor_sync(0xffffffffu, a[k1], (int)ml);
                    const float v0 = __shfl_xor_sync(0xffffffffu, a[k0], (int)ml);
                    const float fs0 = ((popc_ct((unsigned)k0 & slk) & 1) ? -sp : sp);
                    const float fs1 = ((popc_ct((unsigned)k1 & slk) & 1) ? -sp : sp);
                    a[k0] = fmaf(fs0, v1, c * a[k0]);
                    a[k1] = fmaf(fs1, v0, c * a[k1]);
                }
            }
        }
    } else {
        // ---- cross-warp gate via ping-pong shared buffer ----
        constexpr int PH = shared_before(G) & 1;
        constexpr unsigned TMSK = ml | (mw << 5);   // tid-space xor mask
        float* b = sm->buf[PH];
#pragma unroll
        for (int k = 0; k < KREG; k++) b[k * THREADS + tid] = a[k];
        __syncthreads();
        const float* src = b + (tid ^ (int)TMSK);
#pragma unroll
        for (int k = 0; k < KREG; k++) {
            const float v = src[(k ^ (int)mk) * THREADS];
            const float fs = ((popc_ct((unsigned)k & slk) & 1) ? -sp : sp);
            a[k] = fmaf(fs, v, c * a[k]);
        }
    }
}

template<int G>
__device__ __forceinline__ void run_gates(float a[KREG], SmemT* sm, int tid, int tl8) {
    if constexpr (G < NG) {
        apply_gate<G>(a, sm, tid, tl8);
        run_gates<G + 1>(a, sm, tid, tl8);
    }
}

// compile-time measurement sign helpers (avoid ODR-use of namespace CC in device code)
template<int W>
__device__ __forceinline__ float msign_thread(int tl8, float pw) {
    constexpr Circ CCk = make_circ();
    constexpr unsigned mlo = CCk.msel[W] & 255u;
    return (__popc((unsigned)tl8 & mlo) & 1) ? -pw : pw;
}
template<int K, int W>
__device__ __forceinline__ constexpr float msign_k() {
    constexpr Circ CCk = make_circ();
    return (popc_ct((unsigned)K & (CCk.msel[W] >> 8)) & 1) ? -1.0f : 1.0f;
}

// fully-unrolled per-(k,w) measurement accumulation
template<int K, int W>
__device__ __forceinline__ void meas_acc(float& cf, const float h[NQ]) {
    if constexpr (W < NQ) {
        cf += msign_k<K, W>() * h[W];
        meas_acc<K, W + 1>(cf, h);
    }
}
template<int K>
__device__ __forceinline__ void meas_all(float& z, const float a[KREG], const float h[NQ]) {
    if constexpr (K < KREG) {
        float cf = 0.0f;
        meas_acc<K, 0>(cf, h);
        z = fmaf(a[K] * a[K], cf, z);
        meas_all<K + 1>(z, a, h);
    }
}
template<int W>
__device__ __forceinline__ void meas_h(float h[NQ], int tl8, const float* postw) {
    if constexpr (W < NQ) {
        h[W] = msign_thread<W>(tl8, postw[W]);
        meas_h<W + 1>(h, tl8, postw);
    }
}

__global__ __launch_bounds__(THREADS) void dqc_kernel(
    const float* __restrict__ x,
    const float* __restrict__ pre_w,
    const float* __restrict__ pre_b,
    const float* __restrict__ weights,
    const float* __restrict__ post_w,
    const float* __restrict__ post_b,
    float* __restrict__ out)
{
    __shared__ SmemT sm;

    const int tid  = threadIdx.x;
    const int b    = blockIdx.x;
    const int lane = tid & 31;
    const int warp = tid >> 5;
    // thread-part of physical index i (bits 0..7): warp -> bits 0..2, lane -> bits 3..7
    const int tl8 = (lane << 3) | warp;

    // ---------------- pre-layer: 12 dot products of length 512 ----------------
    {
        float2 xv = ((const float2*)(x + (size_t)b * DIN))[tid];
        float acc[NQ];
#pragma unroll
        for (int w = 0; w < NQ; w++) {
            float2 pv = ((const float2*)(pre_w + w * DIN))[tid];
            acc[w] = xv.x * pv.x + xv.y * pv.y;
        }
#pragma unroll
        for (int o = 16; o; o >>= 1)
#pragma unroll
            for (int w = 0; w < NQ; w++)
                acc[w] += __shfl_xor_sync(0xffffffffu, acc[w], o);
        if (lane == 0) {
#pragma unroll
            for (int w = 0; w < NQ; w++) sm.wsum[warp][w] = acc[w];
        }
    }
    __syncthreads();

    // ---------------- angles + gate trig ----------------
    if (tid < NQ) {
        float s = pre_b[tid];
#pragma unroll
        for (int k = 0; k < 8; k++) s += sm.wsum[k][tid];
        float h = s * 0.78539816339744830962f;   // pre * (pi/2) / 2
        float c, sn;
        sincosf(h, &sn, &c);
        const float is2 = 0.70710678118654752440f;
        sm.vv0[tid] = (c - sn) * is2;
        sm.vv1[tid] = (c + sn) * is2;
        sm.postw[tid] = post_w[tid];
    }
    if (tid >= 32 && tid < 32 + NG) {
        int g = tid - 32;
        float h = 0.5f * weights[g];   // [6][12] row-major == gate order
        float c, sn;
        sincosf(h, &sn, &c);
        sm.gc[g] = c; sm.gs[g] = sn;
    }
    __syncthreads();

    // ---------------- product-state init into registers ----------------
    float a[KREG];
    {
        float base = 1.0f;
#pragma unroll
        for (int q = 0; q < 8; q++)
            base *= ((tl8 >> q) & 1) ? sm.vv1[q] : sm.vv0[q];
        float p89[4], pAB[4];
#pragma unroll
        for (int j = 0; j < 4; j++) {
            p89[j] = ((j & 1) ? sm.vv1[8]  : sm.vv0[8])  * ((j & 2) ? sm.vv1[9]  : sm.vv0[9]);
            pAB[j] = ((j & 1) ? sm.vv1[10] : sm.vv0[10]) * ((j & 2) ? sm.vv1[11] : sm.vv0[11]);
        }
#pragma unroll
        for (int k = 0; k < KREG; k++)
            a[k] = base * p89[k & 3] * pAB[k >> 2];
    }

    // ---------------- 72 gates, fully specialized ----------------
    run_gates<0>(a, &sm, tid, tl8);

    // ---------------- measurement fused with post layer ----------------
    float h[NQ];
    meas_h<0>(h, tl8, sm.postw);
    float z = 0.0f;
    meas_all<0>(z, a, h);
#pragma unroll
    for (int o = 16; o; o >>= 1) z += __shfl_xor_sync(0xffffffffu, z, o);
    if (lane == 0) sm.red[warp] = z;
    __syncthreads();
    if (tid == 0) {
        float t = post_b[0];
#pragma unroll
        for (int k = 0; k < 8; k++) t += sm.red[k];
        out[b] = t;
    }
}

extern "C" void kernel_launch(void* const* d_in, const int* in_sizes, int n_in,
                              void* d_out, int out_size) {
    const float* x       = (const float*)d_in[0];
    const float* pre_w   = (const float*)d_in[1];
    const float* pre_b   = (const float*)d_in[2];
    const float* weights = (const float*)d_in[3];
    const float* post_w  = (const float*)d_in[4];
    const float* post_b  = (const float*)d_in[5];
    float* out = (float*)d_out;

    int batch = in_sizes[0] / DIN;   // 8192
    dqc_kernel<<<batch, THREADS>>>(x, pre_w, pre_b, weights, post_w, post_b, out);
}

// round 7
// speedup vs baseline: 3.4281x; 1.1284x over previous
#include <cuda_runtime.h>

#define NQ 12
#define NL 6
#define NG 72          // NL*NQ
#define DIM 4096
#define DIN 512
#define THREADS 64
#define KREG 64        // DIM / THREADS, state amps per thread

// ---------------------------------------------------------------------------
// Compile-time circuit structure (same algebra as R6, which passed):
// CNOT chain folded into per-gate (mask, sel) over GF(2).
//   RY(l,w): pair (i, i^mask), mask = col w of A^-l
//   sign(i) = +s if parity(i & sel)=1 else -s, sel = row w of A^l
//   new(i)  = c*old(i) + sign(i)*old(i^mask)
// Measurement <Z_w> uses sel = row w of A^6.
// ---------------------------------------------------------------------------
struct Circ {
    unsigned mask[NG];
    unsigned sel[NG];
    unsigned msel[NQ];
};

__host__ __device__ constexpr Circ make_circ() {
    Circ c{};
    unsigned Ap[NQ] = {}, Aip[NQ] = {};
    for (int i = 0; i < NQ; i++) { Ap[i] = 1u << i; Aip[i] = 1u << i; }
    for (int l = 0; l < NL; l++) {
        for (int w = 0; w < NQ; w++) {
            c.sel[l * NQ + w] = Ap[w];
            unsigned m = 0;
            for (int i = 0; i < NQ; i++) m |= ((Aip[i] >> w) & 1u) << i;
            c.mask[l * NQ + w] = m;
        }
        unsigned a = 0;
        for (int i = 0; i < NQ; i++) { a ^= Ap[i]; Ap[i] = a; }
        for (int i = NQ - 1; i >= 1; i--) Aip[i] ^= Aip[i - 1];
    }
    for (int w = 0; w < NQ; w++) c.msel[w] = Ap[w];
    return c;
}
constexpr Circ CC = make_circ();

__host__ __device__ constexpr int popc_ct(unsigned x) {
    int n = 0; while (x) { n += x & 1u; x >>= 1; } return n;
}
__host__ __device__ constexpr unsigned topbit(unsigned x) {
    unsigned r = 0;
    for (int b = 31; b >= 0; b--) if ((x >> b) & 1u) { r = 1u << b; break; }
    return r;
}
constexpr bool check_circ() {
    for (int g = 0; g < NG; g++)
        if ((popc_ct(CC.mask[g] & CC.sel[g]) & 1) != 1) return false;
    // at T=64: shared gates (bit0 in mask) must have no register bits in mask
    for (int g = 0; g < NG; g++)
        if ((CC.mask[g] & 1u) && (CC.mask[g] >> 6)) return false;
    return true;
}
static_assert(check_circ(), "circuit structure invariant violated");

// ---------------------------------------------------------------------------
// Layout: physical index i = (k<<6) | tl6,  tl6 = thread-part (6 bits):
//   i bit 0      -> warp bit   (tid>>5)
//   i bits 1..5  -> lane bits  (tid&31)
//   i bits 6..11 -> register k (per-thread, 64 amps)
// Shared buffer layout: buf[k*64 + tid] (store stride-1 per warp; read is a
// tid-space XOR -> bank-conflict-free).
// ---------------------------------------------------------------------------

struct SmemT {
    float buf[DIM];        // 16 KB state buffer for cross-warp gates
    float gc[NG], gs[NG];
    float vv0[NQ], vv1[NQ];
    float wsum[2][NQ];
    float postw[NQ];
    float red[2];
};

template<int G>
__device__ __forceinline__ void apply_gate(float a[KREG], SmemT* sm, int tid, int tl6) {
    constexpr Circ CCk = make_circ();
    constexpr unsigned m   = CCk.mask[G];
    constexpr unsigned sl  = CCk.sel[G];
    constexpr unsigned mk  = m >> 6;          // register-bit part of mask
    constexpr unsigned ml  = (m >> 1) & 31u;  // lane-bit part
    constexpr unsigned mw  = m & 1u;          // warp-bit part
    constexpr unsigned slk = sl >> 6;         // register-bit part of sel
    constexpr unsigned slt = sl & 63u;        // thread-part of sel

    const float c = sm->gc[G];
    const float s = sm->gs[G];
    const int pt = __popc((unsigned)tl6 & slt) & 1;
    const float sp = pt ? s : -s;
    // full sign for register-part k: fs(k) = parity(k&slk) ? -sp : +sp

    if constexpr (mw == 0 && ml == 0) {
        // ---- register-local butterfly (32 pairs) ----
        constexpr unsigned hb = topbit(mk);
#pragma unroll
        for (int k0 = 0; k0 < KREG; k0++) {
            if ((k0 & (int)hb) == 0) {
                const int k1 = k0 ^ (int)mk;
                const float fs0 = ((popc_ct((unsigned)k0 & slk) & 1) ? -sp : sp);
                const float fs1 = ((popc_ct((unsigned)k1 & slk) & 1) ? -sp : sp);
                const float n0 = fmaf(fs0, a[k1], c * a[k0]);
                const float n1 = fmaf(fs1, a[k0], c * a[k1]);
                a[k0] = n0; a[k1] = n1;
            }
        }
    } else if constexpr (mw == 0) {
        // ---- shuffle butterfly (lane exchange) ----
        if constexpr (mk == 0) {
#pragma unroll
            for (int k = 0; k < KREG; k++) {
                const float v = __shfl_xor_sync(0xffffffffu, a[k], (int)ml);
                const float fs = ((popc_ct((unsigned)k & slk) & 1) ? -sp : sp);
                a[k] = fmaf(fs, v, c * a[k]);
            }
        } else {
            constexpr unsigned hb = topbit(mk);
#pragma unroll
            for (int k0 = 0; k0 < KREG; k0++) {
                if ((k0 & (int)hb) == 0) {
                    const int k1 = k0 ^ (int)mk;
                    const float v1 = __shfl_xor_sync(0xffffffffu, a[k1], (int)ml);
                    const float v0 = __shfl_xor_sync(0xffffffffu, a[k0], (int)ml);
                    const float fs0 = ((popc_ct((unsigned)k0 & slk) & 1) ? -sp : sp);
                    const float fs1 = ((popc_ct((unsigned)k1 & slk) & 1) ? -sp : sp);
                    a[k0] = fmaf(fs0, v1, c * a[k0]);
                    a[k1] = fmaf(fs1, v0, c * a[k1]);
                }
            }
        }
    } else {
        // ---- cross-warp gate (mask has no register bits; sel thread-only) ----
        // tid-space XOR mask: i-bit0 -> tid bit5; i-bits1..5 -> tid bits0..4
        constexpr unsigned TMSK = (mw << 5) | ml;
        static_assert(mk == 0, "shared gate with register mask bits");
#pragma unroll
        for (int k = 0; k < KREG; k++) sm->buf[k * THREADS + tid] = a[k];
        __syncthreads();
        const float* src = sm->buf + (tid ^ (int)TMSK);
#pragma unroll
        for (int k = 0; k < KREG; k++) {
            const float v = src[k * THREADS];
            const float fs = ((popc_ct((unsigned)k & slk) & 1) ? -sp : sp);
            a[k] = fmaf(fs, v, c * a[k]);
        }
        __syncthreads();   // protect buffer reuse by the next shared gate
    }
}

template<int G>
__device__ __forceinline__ void run_gates(float a[KREG], SmemT* sm, int tid, int tl6) {
    if constexpr (G < NG) {
        apply_gate<G>(a, sm, tid, tl6);
        run_gates<G + 1>(a, sm, tid, tl6);
    }
}

// measurement helpers (all circuit constants via local constexpr)
template<int W>
__device__ __forceinline__ float msign_thread(int tl6, float pw) {
    constexpr Circ CCk = make_circ();
    constexpr unsigned mlo = CCk.msel[W] & 63u;
    return (__popc((unsigned)tl6 & mlo) & 1) ? -pw : pw;
}
template<int K, int W>
__device__ __forceinline__ constexpr float msign_k() {
    constexpr Circ CCk = make_circ();
    return (popc_ct((unsigned)K & (CCk.msel[W] >> 6)) & 1) ? -1.0f : 1.0f;
}
template<int K, int W>
__device__ __forceinline__ void meas_acc(float& cf, const float h[NQ]) {
    if constexpr (W < NQ) {
        cf += msign_k<K, W>() * h[W];
        meas_acc<K, W + 1>(cf, h);
    }
}
template<int K>
__device__ __forceinline__ void meas_all(float& z, const float a[KREG], const float h[NQ]) {
    if constexpr (K < KREG) {
        float cf = 0.0f;
        meas_acc<K, 0>(cf, h);
        z = fmaf(a[K] * a[K], cf, z);
        meas_all<K + 1>(z, a, h);
    }
}
template<int W>
__device__ __forceinline__ void meas_h(float h[NQ], int tl6, const float* postw) {
    if constexpr (W < NQ) {
        h[W] = msign_thread<W>(tl6, postw[W]);
        meas_h<W + 1>(h, tl6, postw);
    }
}

__global__ __launch_bounds__(THREADS) void dqc_kernel(
    const float* __restrict__ x,
    const float* __restrict__ pre_w,
    const float* __restrict__ pre_b,
    const float* __restrict__ weights,
    const float* __restrict__ post_w,
    const float* __restrict__ post_b,
    float* __restrict__ out)
{
    __shared__ SmemT sm;

    const int tid  = threadIdx.x;
    const int b    = blockIdx.x;
    const int lane = tid & 31;
    const int warp = tid >> 5;
    // thread-part of physical index i: warp -> i bit0, lane -> i bits1..5
    const int tl6 = warp | (lane << 1);

    // ---------------- pre-layer: 12 dot products of length 512 ----------------
    {
        const float4* xr = (const float4*)(x + (size_t)b * DIN);
        const float4 xa = xr[tid * 2];
        const float4 xb = xr[tid * 2 + 1];
        float acc[NQ];
#pragma unroll
        for (int w = 0; w < NQ; w++) {
            const float4* pr = (const float4*)(pre_w + w * DIN);
            const float4 pa = pr[tid * 2];
            const float4 pb = pr[tid * 2 + 1];
            float d = xa.x * pa.x + xa.y * pa.y + xa.z * pa.z + xa.w * pa.w;
            d += xb.x * pb.x + xb.y * pb.y + xb.z * pb.z + xb.w * pb.w;
            acc[w] = d;
        }
#pragma unroll
        for (int o = 16; o; o >>= 1)
#pragma unroll
            for (int w = 0; w < NQ; w++)
                acc[w] += __shfl_xor_sync(0xffffffffu, acc[w], o);
        if (lane == 0) {
#pragma unroll
            for (int w = 0; w < NQ; w++) sm.wsum[warp][w] = acc[w];
        }
    }
    __syncthreads();

    // ---------------- angles + gate trig ----------------
    if (tid < NQ) {
        float s = pre_b[tid] + sm.wsum[0][tid] + sm.wsum[1][tid];
        float h = s * 0.78539816339744830962f;   // pre * (pi/2) / 2
        float c, sn;
        sincosf(h, &sn, &c);
        const float is2 = 0.70710678118654752440f;
        sm.vv0[tid] = (c - sn) * is2;
        sm.vv1[tid] = (c + sn) * is2;
        sm.postw[tid] = post_w[tid];
    }
    {
        int g = tid;                       // gates 0..63
        float h = 0.5f * weights[g];
        float c, sn;
        sincosf(h, &sn, &c);
        sm.gc[g] = c; sm.gs[g] = sn;
        if (tid < NG - THREADS) {          // gates 64..71
            g = tid + THREADS;
            h = 0.5f * weights[g];
            sincosf(h, &sn, &c);
            sm.gc[g] = c; sm.gs[g] = sn;
        }
    }
    __syncthreads();

    // ---------------- product-state init into registers ----------------
    float a[KREG];
    {
        float base = 1.0f;
#pragma unroll
        for (int q = 0; q < 6; q++)
            base *= ((tl6 >> q) & 1) ? sm.vv1[q] : sm.vv0[q];
        float p67[4], p89[4], pAB[4];
#pragma unroll
        for (int j = 0; j < 4; j++) {
            p67[j] = ((j & 1) ? sm.vv1[6]  : sm.vv0[6])  * ((j & 2) ? sm.vv1[7]  : sm.vv0[7]);
            p89[j] = ((j & 1) ? sm.vv1[8]  : sm.vv0[8])  * ((j & 2) ? sm.vv1[9]  : sm.vv0[9]);
            pAB[j] = ((j & 1) ? sm.vv1[10] : sm.vv0[10]) * ((j & 2) ? sm.vv1[11] : sm.vv0[11]);
        }
#pragma unroll
        for (int k = 0; k < KREG; k++)
            a[k] = (base * p67[k & 3]) * (p89[(k >> 2) & 3] * pAB[(k >> 4) & 3]);
    }

    // ---------------- 72 gates, fully specialized ----------------
    run_gates<0>(a, &sm, tid, tl6);

    // ---------------- measurement fused with post layer ----------------
    float h[NQ];
    meas_h<0>(h, tl6, sm.postw);
    float z = 0.0f;
    meas_all<0>(z, a, h);
#pragma unroll
    for (int o = 16; o; o >>= 1) z += __shfl_xor_sync(0xffffffffu, z, o);
    if (lane == 0) sm.red[warp] = z;
    __syncthreads();
    if (tid == 0) {
        out[b] = post_b[0] + sm.red[0] + sm.red[1];
    }
}

extern "C" void kernel_launch(void* const* d_in, const int* in_sizes, int n_in,
                              void* d_out, int out_size) {
    const float* x       = (const float*)d_in[0];
    const float* pre_w   = (const float*)d_in[1];
    const float* pre_b   = (const float*)d_in[2];
    const float* weights = (const float*)d_in[3];
    const float* post_w  = (const float*)d_in[4];
    const float* post_b  = (const float*)d_in[5];
    float* out = (float*)d_out;

    int batch = in_sizes[0] / DIN;   // 8192
    dqc_kernel<<<batch, THREADS>>>(x, pre_w, pre_b, weights, post_w, post_b, out);
}

// round 8
// speedup vs baseline: 3.8948x; 1.1361x over previous
#include <cuda_runtime.h>

#define NQ 12
#define NL 6
#define NG 72          // NL*NQ
#define DIM 4096
#define DIN 512
#define THREADS 64
#define KREG 64        // amps per thread
#define NPACK 32       // f32x2 packs per thread (pack bit = qubit 6)

// ---------------------------------------------------------------------------
// Compile-time circuit structure (same algebra as R6/R7, which passed):
//   RY(l,w): pair (i, i^mask), mask = col w of A^-l
//   sign(i) = +s if parity(i & sel)=1 else -s, sel = row w of A^l
//   new(i)  = c*old(i) + sign(i)*old(i^mask)
// Measurement <Z_w> uses sel = row w of A^6.
// ---------------------------------------------------------------------------
struct Circ {
    unsigned mask[NG];
    unsigned sel[NG];
    unsigned msel[NQ];
};

__host__ __device__ constexpr Circ make_circ() {
    Circ c{};
    unsigned Ap[NQ] = {}, Aip[NQ] = {};
    for (int i = 0; i < NQ; i++) { Ap[i] = 1u << i; Aip[i] = 1u << i; }
    for (int l = 0; l < NL; l++) {
        for (int w = 0; w < NQ; w++) {
            c.sel[l * NQ + w] = Ap[w];
            unsigned m = 0;
            for (int i = 0; i < NQ; i++) m |= ((Aip[i] >> w) & 1u) << i;
            c.mask[l * NQ + w] = m;
        }
        unsigned a = 0;
        for (int i = 0; i < NQ; i++) { a ^= Ap[i]; Ap[i] = a; }
        for (int i = NQ - 1; i >= 1; i--) Aip[i] ^= Aip[i - 1];
    }
    for (int w = 0; w < NQ; w++) c.msel[w] = Ap[w];
    return c;
}
constexpr Circ CC = make_circ();

__host__ __device__ constexpr int popc_ct(unsigned x) {
    int n = 0; while (x) { n += x & 1u; x >>= 1; } return n;
}
__host__ __device__ constexpr unsigned topbit(unsigned x) {
    unsigned r = 0;
    for (int b = 31; b >= 0; b--) if ((x >> b) & 1u) { r = 1u << b; break; }
    return r;
}
constexpr bool check_circ() {
    for (int g = 0; g < NG; g++)
        if ((popc_ct(CC.mask[g] & CC.sel[g]) & 1) != 1) return false;
    // shared gates (mask bit0) must have no register-space mask bits at T=64
    for (int g = 0; g < NG; g++)
        if ((CC.mask[g] & 1u) && (CC.mask[g] >> 6)) return false;
    return true;
}
static_assert(check_circ(), "circuit structure invariant violated");

// ---------------------------------------------------------------------------
// Packed f32x2 helpers (Blackwell FFMA2 path; only reachable via PTX)
// ---------------------------------------------------------------------------
typedef unsigned long long u64;

__device__ __forceinline__ u64 pk2(float lo, float hi) {
    u64 r; asm("mov.b64 %0, {%1, %2};" : "=l"(r) : "f"(lo), "f"(hi)); return r;
}
__device__ __forceinline__ void upk2(u64 v, float& lo, float& hi) {
    asm("mov.b64 {%0, %1}, %2;" : "=f"(lo), "=f"(hi) : "l"(v));
}
__device__ __forceinline__ u64 swap2(u64 v) {
    float lo, hi; upk2(v, lo, hi); return pk2(hi, lo);
}
__device__ __forceinline__ u64 mul2(u64 a, u64 b) {
    u64 d; asm("mul.rn.f32x2 %0, %1, %2;" : "=l"(d) : "l"(a), "l"(b)); return d;
}
__device__ __forceinline__ u64 fma2(u64 a, u64 b, u64 c) {
    u64 d; asm("fma.rn.f32x2 %0, %1, %2, %3;" : "=l"(d) : "l"(a), "l"(b), "l"(c)); return d;
}
__device__ __forceinline__ u64 shflx2(u64 v, int m) {
    return __shfl_xor_sync(0xffffffffu, v, m);
}

// ---------------------------------------------------------------------------
// Layout: physical index i = (k<<6) | tl6, tl6 = thread-part (6 bits):
//   i bit 0      -> warp bit   (tid>>5)
//   i bits 1..5  -> lane bits  (tid&31)
//   i bits 6..11 -> per-thread k;  k bit 0 = f32x2 component, k bits 1..5 = pack j
// Shared buffer: buf[j*64 + tid] as u64 (conflict-free, XOR partner in tid-space)
// ---------------------------------------------------------------------------

struct SmemT {
    u64 buf[NPACK * THREADS];   // 16 KB state buffer for cross-warp gates
    float gc[NG], gs[NG];
    float vv0[NQ], vv1[NQ];
    float wsum[2][NQ];
    float postw[NQ];
    float red[2];
};

template<int G>
__device__ __forceinline__ void apply_gate(u64 A[NPACK], SmemT* sm, int tid, int tl6) {
    constexpr Circ CCk = make_circ();
    constexpr unsigned m    = CCk.mask[G];
    constexpr unsigned sl   = CCk.sel[G];
    constexpr unsigned mk   = m >> 6;          // k-space mask
    constexpr unsigned ml   = (m >> 1) & 31u;  // lane-space mask
    constexpr unsigned mw   = m & 1u;          // warp bit
    constexpr unsigned mkp  = mk >> 1;         // pack-index part of mask
    constexpr unsigned mb6  = mk & 1u;         // component-swap flag
    constexpr unsigned slk  = sl >> 6;
    constexpr unsigned slt  = sl & 63u;        // thread-part of sel
    constexpr unsigned slkp = slk >> 1;        // pack-index part of sel
    constexpr unsigned slc  = slk & 1u;        // component bit of sel

    const float c = sm->gc[G];
    const float s = sm->gs[G];
    const int pt = __popc((unsigned)tl6 & slt) & 1;
    const float sp = pt ? s : -s;
    const float f1 = slc ? -sp : sp;
    const u64 C2 = pk2(c, c);
    const u64 FP = pk2(sp, f1);
    const u64 FN = pk2(-sp, -f1);
    // fsvec(j) = parity(j & slkp) ? FN : FP

    if constexpr (mw == 0 && ml == 0) {
        // ---- register-local packed butterfly ----
        if constexpr (mkp == 0) {
            static_assert(mb6 == 1, "empty register mask");
#pragma unroll
            for (int j = 0; j < NPACK; j++) {
                const u64 fs = (popc_ct((unsigned)j & slkp) & 1) ? FN : FP;
                A[j] = fma2(fs, swap2(A[j]), mul2(C2, A[j]));
            }
        } else {
            constexpr unsigned hbp = topbit(mkp);
#pragma unroll
            for (int j0 = 0; j0 < NPACK; j0++) {
                if ((j0 & (int)hbp) == 0) {
                    const int j1 = j0 ^ (int)mkp;
                    const u64 fs0 = (popc_ct((unsigned)j0 & slkp) & 1) ? FN : FP;
                    const u64 fs1 = (popc_ct((unsigned)j1 & slkp) & 1) ? FN : FP;
                    u64 p0 = A[j1], p1 = A[j0];
                    if constexpr (mb6) { p0 = swap2(p0); p1 = swap2(p1); }
                    const u64 n0 = fma2(fs0, p0, mul2(C2, A[j0]));
                    const u64 n1 = fma2(fs1, p1, mul2(C2, A[j1]));
                    A[j0] = n0; A[j1] = n1;
                }
            }
        }
    } else if constexpr (mw == 0) {
        // ---- shuffle butterfly (lane exchange) ----
        if constexpr (mkp == 0) {
#pragma unroll
            for (int j = 0; j < NPACK; j++) {
                u64 v = shflx2(A[j], (int)ml);
                if constexpr (mb6) v = swap2(v);
                const u64 fs = (popc_ct((unsigned)j & slkp) & 1) ? FN : FP;
                A[j] = fma2(fs, v, mul2(C2, A[j]));
            }
        } else {
            constexpr unsigned hbp = topbit(mkp);
#pragma unroll
            for (int j0 = 0; j0 < NPACK; j0++) {
                if ((j0 & (int)hbp) == 0) {
                    const int j1 = j0 ^ (int)mkp;
                    u64 v1 = shflx2(A[j1], (int)ml);
                    u64 v0 = shflx2(A[j0], (int)ml);
                    if constexpr (mb6) { v1 = swap2(v1); v0 = swap2(v0); }
                    const u64 fs0 = (popc_ct((unsigned)j0 & slkp) & 1) ? FN : FP;
                    const u64 fs1 = (popc_ct((unsigned)j1 & slkp) & 1) ? FN : FP;
                    A[j0] = fma2(fs0, v1, mul2(C2, A[j0]));
                    A[j1] = fma2(fs1, v0, mul2(C2, A[j1]));
                }
            }
        }
    } else {
        // ---- cross-warp gate via shared (mask has no k-space bits) ----
        static_assert(mk == 0, "shared gate with register mask bits");
        constexpr unsigned TMSK = (mw << 5) | ml;   // tid-space xor
#pragma unroll
        for (int j = 0; j < NPACK; j++) sm->buf[j * THREADS + tid] = A[j];
        __syncthreads();
        const u64* src = sm->buf + (tid ^ (int)TMSK);
#pragma unroll
        for (int j = 0; j < NPACK; j++) {
            const u64 v = src[j * THREADS];
            const u64 fs = (popc_ct((unsigned)j & slkp) & 1) ? FN : FP;
            A[j] = fma2(fs, v, mul2(C2, A[j]));
        }
        __syncthreads();
    }
}

template<int G>
__device__ __forceinline__ void run_gates(u64 A[NPACK], SmemT* sm, int tid, int tl6) {
    if constexpr (G < NG) {
        apply_gate<G>(A, sm, tid, tl6);
        run_gates<G + 1>(A, sm, tid, tl6);
    }
}

// measurement helpers
template<int W>
__device__ __forceinline__ float msign_thread(int tl6, float pw) {
    constexpr Circ CCk = make_circ();
    constexpr unsigned mlo = CCk.msel[W] & 63u;
    return (__popc((unsigned)tl6 & mlo) & 1) ? -pw : pw;
}
template<int K, int W>
__device__ __forceinline__ constexpr float msign_k() {
    constexpr Circ CCk = make_circ();
    return (popc_ct((unsigned)K & (CCk.msel[W] >> 6)) & 1) ? -1.0f : 1.0f;
}
template<int K, int W>
__device__ __forceinline__ void meas_acc(float& cf, const float h[NQ]) {
    if constexpr (W < NQ) {
        cf += msign_k<K, W>() * h[W];
        meas_acc<K, W + 1>(cf, h);
    }
}
template<int J>
__device__ __forceinline__ void meas_packs(float& z, const u64 A[NPACK], const float h[NQ]) {
    if constexpr (J < NPACK) {
        float a0, a1;
        upk2(A[J], a0, a1);
        float cf0 = 0.0f, cf1 = 0.0f;
        meas_acc<2 * J, 0>(cf0, h);
        meas_acc<2 * J + 1, 0>(cf1, h);
        z = fmaf(a0 * a0, cf0, z);
        z = fmaf(a1 * a1, cf1, z);
        meas_packs<J + 1>(z, A, h);
    }
}
template<int W>
__device__ __forceinline__ void meas_h(float h[NQ], int tl6, const float* postw) {
    if constexpr (W < NQ) {
        h[W] = msign_thread<W>(tl6, postw[W]);
        meas_h<W + 1>(h, tl6, postw);
    }
}

__global__ __launch_bounds__(THREADS) void dqc_kernel(
    const float* __restrict__ x,
    const float* __restrict__ pre_w,
    const float* __restrict__ pre_b,
    const float* __restrict__ weights,
    const float* __restrict__ post_w,
    const float* __restrict__ post_b,
    float* __restrict__ out)
{
    __shared__ SmemT sm;

    const int tid  = threadIdx.x;
    const int b    = blockIdx.x;
    const int lane = tid & 31;
    const int warp = tid >> 5;
    const int tl6 = warp | (lane << 1);   // thread-part of physical index

    // ---------------- pre-layer: 12 dot products of length 512 ----------------
    {
        const float4* xr = (const float4*)(x + (size_t)b * DIN);
        const float4 xa = xr[tid * 2];
        const float4 xb = xr[tid * 2 + 1];
        float acc[NQ];
#pragma unroll
        for (int w = 0; w < NQ; w++) {
            const float4* pr = (const float4*)(pre_w + w * DIN);
            const float4 pa = pr[tid * 2];
            const float4 pb = pr[tid * 2 + 1];
            float d = xa.x * pa.x + xa.y * pa.y + xa.z * pa.z + xa.w * pa.w;
            d += xb.x * pb.x + xb.y * pb.y + xb.z * pb.z + xb.w * pb.w;
            acc[w] = d;
        }
#pragma unroll
        for (int o = 16; o; o >>= 1)
#pragma unroll
            for (int w = 0; w < NQ; w++)
                acc[w] += __shfl_xor_sync(0xffffffffu, acc[w], o);
        if (lane == 0) {
#pragma unroll
            for (int w = 0; w < NQ; w++) sm.wsum[warp][w] = acc[w];
        }
    }
    __syncthreads();

    // ---------------- angles + gate trig ----------------
    if (tid < NQ) {
        float s = pre_b[tid] + sm.wsum[0][tid] + sm.wsum[1][tid];
        float h = s * 0.78539816339744830962f;   // pre * (pi/2) / 2
        float c, sn;
        sincosf(h, &sn, &c);
        const float is2 = 0.70710678118654752440f;
        sm.vv0[tid] = (c - sn) * is2;
        sm.vv1[tid] = (c + sn) * is2;
        sm.postw[tid] = post_w[tid];
    }
    {
        int g = tid;                       // gates 0..63
        float h = 0.5f * weights[g];
        float c, sn;
        sincosf(h, &sn, &c);
        sm.gc[g] = c; sm.gs[g] = sn;
        if (tid < NG - THREADS) {          // gates 64..71
            g = tid + THREADS;
            h = 0.5f * weights[g];
            sincosf(h, &sn, &c);
            sm.gc[g] = c; sm.gs[g] = sn;
        }
    }
    __syncthreads();

    // ---------------- product-state init into packed registers ----------------
    u64 A[NPACK];
    {
        float base = 1.0f;
#pragma unroll
        for (int q = 0; q < 6; q++)
            base *= ((tl6 >> q) & 1) ? sm.vv1[q] : sm.vv0[q];
        float p67[4], p89[4], pAB[4];
#pragma unroll
        for (int j = 0; j < 4; j++) {
            p67[j] = ((j & 1) ? sm.vv1[6]  : sm.vv0[6])  * ((j & 2) ? sm.vv1[7]  : sm.vv0[7]);
            p89[j] = ((j & 1) ? sm.vv1[8]  : sm.vv0[8])  * ((j & 2) ? sm.vv1[9]  : sm.vv0[9]);
            pAB[j] = ((j & 1) ? sm.vv1[10] : sm.vv0[10]) * ((j & 2) ? sm.vv1[11] : sm.vv0[11]);
        }
#pragma unroll
        for (int j = 0; j < NPACK; j++) {
            const int k0 = 2 * j, k1 = 2 * j + 1;
            const float rest = p89[(j >> 1) & 3] * pAB[(j >> 3) & 3];
            const float a0 = (base * p67[k0 & 3]) * rest;
            const float a1 = (base * p67[k1 & 3]) * rest;
            A[j] = pk2(a0, a1);
        }
    }

    // ---------------- 72 gates, fully specialized, packed ----------------
    run_gates<0>(A, &sm, tid, tl6);

    // ---------------- measurement fused with post layer ----------------
    float h[NQ];
    meas_h<0>(h, tl6, sm.postw);
    float z = 0.0f;
    meas_packs<0>(z, A, h);
#pragma unroll
    for (int o = 16; o; o >>= 1) z += __shfl_xor_sync(0xffffffffu, z, o);
    if (lane == 0) sm.red[warp] = z;
    __syncthreads();
    if (tid == 0) {
        out[b] = post_b[0] + sm.red[0] + sm.red[1];
    }
}

extern "C" void kernel_launch(void* const* d_in, const int* in_sizes, int n_in,
                              void* d_out, int out_size) {
    const float* x       = (const float*)d_in[0];
    const float* pre_w   = (const float*)d_in[1];
    const float* pre_b   = (const float*)d_in[2];
    const float* weights = (const float*)d_in[3];
    const float* post_w  = (const float*)d_in[4];
    const float* post_b  = (const float*)d_in[5];
    float* out = (float*)d_out;

    int batch = in_sizes[0] / DIN;   // 8192
    dqc_kernel<<<batch, THREADS>>>(x, pre_w, pre_b, weights, post_w, post_b, out);
}

// round 9
// speedup vs baseline: 4.7979x; 1.2319x over previous
#include <cuda_runtime.h>

#define NQ 12
#define NL 6
#define NG 72          // NL*NQ
#define DIM 4096
#define DIN 512
#define THREADS 64
#define KREG 64        // amps per thread
#define NPACK 32       // f32x2 packs per thread (pack bit = qubit 6)

// ---------------------------------------------------------------------------
// Compile-time circuit structure (same algebra as R6-R8, which passed):
//   RY(l,w): pair (i, i^mask), mask = col w of A^-l
//   sign(i) = +1 if parity(i & sel)=1 else -1, sel = row w of A^l
// Tan-lifting: new(i) = old(i) + sign(i)*t*old(i^mask), t = tan(h); the uniform
// factor c=cos(h) per gate is deferred and (prod c)^2 is folded into the
// measurement coefficients.
// Measurement <Z_w> uses sel = row w of A^6.
// ---------------------------------------------------------------------------
struct Circ {
    unsigned mask[NG];
    unsigned sel[NG];
    unsigned msel[NQ];
};

__host__ __device__ constexpr Circ make_circ() {
    Circ c{};
    unsigned Ap[NQ] = {}, Aip[NQ] = {};
    for (int i = 0; i < NQ; i++) { Ap[i] = 1u << i; Aip[i] = 1u << i; }
    for (int l = 0; l < NL; l++) {
        for (int w = 0; w < NQ; w++) {
            c.sel[l * NQ + w] = Ap[w];
            unsigned m = 0;
            for (int i = 0; i < NQ; i++) m |= ((Aip[i] >> w) & 1u) << i;
            c.mask[l * NQ + w] = m;
        }
        unsigned a = 0;
        for (int i = 0; i < NQ; i++) { a ^= Ap[i]; Ap[i] = a; }
        for (int i = NQ - 1; i >= 1; i--) Aip[i] ^= Aip[i - 1];
    }
    for (int w = 0; w < NQ; w++) c.msel[w] = Ap[w];
    return c;
}
constexpr Circ CC = make_circ();

__host__ __device__ constexpr int popc_ct(unsigned x) {
    int n = 0; while (x) { n += x & 1u; x >>= 1; } return n;
}
__host__ __device__ constexpr unsigned topbit(unsigned x) {
    unsigned r = 0;
    for (int b = 31; b >= 0; b--) if ((x >> b) & 1u) { r = 1u << b; break; }
    return r;
}
constexpr bool check_circ() {
    for (int g = 0; g < NG; g++)
        if ((popc_ct(CC.mask[g] & CC.sel[g]) & 1) != 1) return false;
    for (int g = 0; g < NG; g++)
        if ((CC.mask[g] & 1u) && (CC.mask[g] >> 6)) return false;
    return true;
}
static_assert(check_circ(), "circuit structure invariant violated");

// ---------------------------------------------------------------------------
// Packed f32x2 helpers (FFMA2 only reachable via PTX)
// ---------------------------------------------------------------------------
typedef unsigned long long u64;

__device__ __forceinline__ u64 pk2(float lo, float hi) {
    u64 r; asm("mov.b64 %0, {%1, %2};" : "=l"(r) : "f"(lo), "f"(hi)); return r;
}
__device__ __forceinline__ void upk2(u64 v, float& lo, float& hi) {
    asm("mov.b64 {%0, %1}, %2;" : "=f"(lo), "=f"(hi) : "l"(v));
}
__device__ __forceinline__ u64 swap2(u64 v) {
    float lo, hi; upk2(v, lo, hi); return pk2(hi, lo);
}
__device__ __forceinline__ u64 fma2(u64 a, u64 b, u64 c) {
    u64 d; asm("fma.rn.f32x2 %0, %1, %2, %3;" : "=l"(d) : "l"(a), "l"(b), "l"(c)); return d;
}
__device__ __forceinline__ u64 shflx2(u64 v, int m) {
    return __shfl_xor_sync(0xffffffffu, v, m);
}

// ---------------------------------------------------------------------------
// Layout: physical index i = (k<<6) | tl6, tl6 = thread-part (6 bits):
//   i bit 0      -> warp bit   (tid>>5)
//   i bits 1..5  -> lane bits  (tid&31)
//   i bits 6..11 -> per-thread k;  k bit 0 = f32x2 component, k bits 1..5 = pack j
// ---------------------------------------------------------------------------

struct SmemT {
    u64 buf[NPACK * THREADS];   // 16 KB state buffer for cross-warp gates
    float gt[NG];               // tan(h) per gate
    float vv0[NQ], vv1[NQ];
    float wsum[2][NQ];
    float postw[NQ];
    float red[2];
    float cred[2];              // per-warp partial products of cos
};

template<int G>
__device__ __forceinline__ void apply_gate(u64 A[NPACK], SmemT* sm, int tid, int tl6) {
    constexpr Circ CCk = make_circ();
    constexpr unsigned m    = CCk.mask[G];
    constexpr unsigned sl   = CCk.sel[G];
    constexpr unsigned mk   = m >> 6;          // k-space mask
    constexpr unsigned ml   = (m >> 1) & 31u;  // lane-space mask
    constexpr unsigned mw   = m & 1u;          // warp bit
    constexpr unsigned mkp  = mk >> 1;         // pack-index part of mask
    constexpr unsigned mb6  = mk & 1u;         // component-swap flag
    constexpr unsigned slk  = sl >> 6;
    constexpr unsigned slt  = sl & 63u;        // thread-part of sel
    constexpr unsigned slkp = slk >> 1;        // pack-index part of sel
    constexpr unsigned slc  = slk & 1u;        // component bit of sel

    const float t = sm->gt[G];
    const int pt = __popc((unsigned)tl6 & slt) & 1;
    const float sp = pt ? t : -t;
    const float f1 = slc ? -sp : sp;
    const u64 FP = pk2(sp, f1);
    const u64 FN = pk2(-sp, -f1);
    // fsvec(j) = parity(j & slkp) ? FN : FP

    if constexpr (mw == 0 && ml == 0) {
        // ---- register-local lifting butterfly ----
        if constexpr (mkp == 0) {
            static_assert(mb6 == 1, "empty register mask");
#pragma unroll
            for (int j = 0; j < NPACK; j++) {
                const u64 fs = (popc_ct((unsigned)j & slkp) & 1) ? FN : FP;
                A[j] = fma2(fs, swap2(A[j]), A[j]);
            }
        } else {
            constexpr unsigned hbp = topbit(mkp);
#pragma unroll
            for (int j0 = 0; j0 < NPACK; j0++) {
                if ((j0 & (int)hbp) == 0) {
                    const int j1 = j0 ^ (int)mkp;
                    const u64 fs0 = (popc_ct((unsigned)j0 & slkp) & 1) ? FN : FP;
                    const u64 fs1 = (popc_ct((unsigned)j1 & slkp) & 1) ? FN : FP;
                    u64 p0 = A[j1], p1 = A[j0];
                    if constexpr (mb6) { p0 = swap2(p0); p1 = swap2(p1); }
                    const u64 n0 = fma2(fs0, p0, A[j0]);
                    const u64 n1 = fma2(fs1, p1, A[j1]);
                    A[j0] = n0; A[j1] = n1;
                }
            }
        }
    } else if constexpr (mw == 0) {
        // ---- shuffle lifting (lane exchange) ----
        if constexpr (mkp == 0) {
#pragma unroll
            for (int j = 0; j < NPACK; j++) {
                u64 v = shflx2(A[j], (int)ml);
                if constexpr (mb6) v = swap2(v);
                const u64 fs = (popc_ct((unsigned)j & slkp) & 1) ? FN : FP;
                A[j] = fma2(fs, v, A[j]);
            }
        } else {
            constexpr unsigned hbp = topbit(mkp);
#pragma unroll
            for (int j0 = 0; j0 < NPACK; j0++) {
                if ((j0 & (int)hbp) == 0) {
                    const int j1 = j0 ^ (int)mkp;
                    u64 v1 = shflx2(A[j1], (int)ml);
                    u64 v0 = shflx2(A[j0], (int)ml);
                    if constexpr (mb6) { v1 = swap2(v1); v0 = swap2(v0); }
                    const u64 fs0 = (popc_ct((unsigned)j0 & slkp) & 1) ? FN : FP;
                    const u64 fs1 = (popc_ct((unsigned)j1 & slkp) & 1) ? FN : FP;
                    A[j0] = fma2(fs0, v1, A[j0]);
                    A[j1] = fma2(fs1, v0, A[j1]);
                }
            }
        }
    } else {
        // ---- cross-warp lifting via shared (mask has no k-space bits) ----
        static_assert(mk == 0, "shared gate with register mask bits");
        constexpr unsigned TMSK = (mw << 5) | ml;   // tid-space xor
#pragma unroll
        for (int j = 0; j < NPACK; j++) sm->buf[j * THREADS + tid] = A[j];
        __syncthreads();
        const u64* src = sm->buf + (tid ^ (int)TMSK);
#pragma unroll
        for (int j = 0; j < NPACK; j++) {
            const u64 v = src[j * THREADS];
            const u64 fs = (popc_ct((unsigned)j & slkp) & 1) ? FN : FP;
            A[j] = fma2(fs, v, A[j]);
        }
        __syncthreads();
    }
}

template<int G>
__device__ __forceinline__ void run_gates(u64 A[NPACK], SmemT* sm, int tid, int tl6) {
    if constexpr (G < NG) {
        apply_gate<G>(A, sm, tid, tl6);
        run_gates<G + 1>(A, sm, tid, tl6);
    }
}

// measurement helpers
template<int W>
__device__ __forceinline__ float msign_thread(int tl6, float pw) {
    constexpr Circ CCk = make_circ();
    constexpr unsigned mlo = CCk.msel[W] & 63u;
    return (__popc((unsigned)tl6 & mlo) & 1) ? -pw : pw;
}
template<int K, int W>
__device__ __forceinline__ constexpr float msign_k() {
    constexpr Circ CCk = make_circ();
    return (popc_ct((unsigned)K & (CCk.msel[W] >> 6)) & 1) ? -1.0f : 1.0f;
}
template<int K, int W>
__device__ __forceinline__ void meas_acc(float& cf, const float h[NQ]) {
    if constexpr (W < NQ) {
        cf += msign_k<K, W>() * h[W];
        meas_acc<K, W + 1>(cf, h);
    }
}
template<int J>
__device__ __forceinline__ void meas_packs(float& z, const u64 A[NPACK], const float h[NQ]) {
    if constexpr (J < NPACK) {
        float a0, a1;
        upk2(A[J], a0, a1);
        float cf0 = 0.0f, cf1 = 0.0f;
        meas_acc<2 * J, 0>(cf0, h);
        meas_acc<2 * J + 1, 0>(cf1, h);
        z = fmaf(a0 * a0, cf0, z);
        z = fmaf(a1 * a1, cf1, z);
        meas_packs<J + 1>(z, A, h);
    }
}
template<int W>
__device__ __forceinline__ void meas_h(float h[NQ], int tl6, const float* postw, float s2) {
    if constexpr (W < NQ) {
        h[W] = msign_thread<W>(tl6, postw[W] * s2);
        meas_h<W + 1>(h, tl6, postw, s2);
    }
}

__global__ __launch_bounds__(THREADS) void dqc_kernel(
    const float* __restrict__ x,
    const float* __restrict__ pre_w,
    const float* __restrict__ pre_b,
    const float* __restrict__ weights,
    const float* __restrict__ post_w,
    const float* __restrict__ post_b,
    float* __restrict__ out)
{
    __shared__ SmemT sm;

    const int tid  = threadIdx.x;
    const int b    = blockIdx.x;
    const int lane = tid & 31;
    const int warp = tid >> 5;
    const int tl6 = warp | (lane << 1);   // thread-part of physical index

    // ---------------- pre-layer: 12 dot products of length 512 ----------------
    {
        const float4* xr = (const float4*)(x + (size_t)b * DIN);
        const float4 xa = xr[tid * 2];
        const float4 xb = xr[tid * 2 + 1];
        float acc[NQ];
#pragma unroll
        for (int w = 0; w < NQ; w++) {
            const float4* pr = (const float4*)(pre_w + w * DIN);
            const float4 pa = pr[tid * 2];
            const float4 pb = pr[tid * 2 + 1];
            float d = xa.x * pa.x + xa.y * pa.y + xa.z * pa.z + xa.w * pa.w;
            d += xb.x * pb.x + xb.y * pb.y + xb.z * pb.z + xb.w * pb.w;
            acc[w] = d;
        }
#pragma unroll
        for (int o = 16; o; o >>= 1)
#pragma unroll
            for (int w = 0; w < NQ; w++)
                acc[w] += __shfl_xor_sync(0xffffffffu, acc[w], o);
        if (lane == 0) {
#pragma unroll
            for (int w = 0; w < NQ; w++) sm.wsum[warp][w] = acc[w];
        }
    }
    __syncthreads();

    // ---------------- angles + gate tan + cos product ----------------
    if (tid < NQ) {
        float s = pre_b[tid] + sm.wsum[0][tid] + sm.wsum[1][tid];
        float h = s * 0.78539816339744830962f;   // pre * (pi/2) / 2
        float c, sn;
        sincosf(h, &sn, &c);
        const float is2 = 0.70710678118654752440f;
        sm.vv0[tid] = (c - sn) * is2;
        sm.vv1[tid] = (c + sn) * is2;
        sm.postw[tid] = post_w[tid];
    }
    {
        float cp = 1.0f;
        int g = tid;                       // gates 0..63
        float h = 0.5f * weights[g];
        float c, sn;
        sincosf(h, &sn, &c);
        sm.gt[g] = sn / c;
        cp = c;
        if (tid < NG - THREADS) {          // gates 64..71
            g = tid + THREADS;
            h = 0.5f * weights[g];
            sincosf(h, &sn, &c);
            sm.gt[g] = sn / c;
            cp *= c;
        }
        // block-wide product of cos values
#pragma unroll
        for (int o = 16; o; o >>= 1) cp *= __shfl_xor_sync(0xffffffffu, cp, o);
        if (lane == 0) sm.cred[warp] = cp;
    }
    __syncthreads();

    // ---------------- product-state init into packed registers ----------------
    u64 A[NPACK];
    {
        float base = 1.0f;
#pragma unroll
        for (int q = 0; q < 6; q++)
            base *= ((tl6 >> q) & 1) ? sm.vv1[q] : sm.vv0[q];
        float p67[4], p89[4], pAB[4];
#pragma unroll
        for (int j = 0; j < 4; j++) {
            p67[j] = ((j & 1) ? sm.vv1[6]  : sm.vv0[6])  * ((j & 2) ? sm.vv1[7]  : sm.vv0[7]);
            p89[j] = ((j & 1) ? sm.vv1[8]  : sm.vv0[8])  * ((j & 2) ? sm.vv1[9]  : sm.vv0[9]);
            pAB[j] = ((j & 1) ? sm.vv1[10] : sm.vv0[10]) * ((j & 2) ? sm.vv1[11] : sm.vv0[11]);
        }
#pragma unroll
        for (int j = 0; j < NPACK; j++) {
            const int k0 = 2 * j, k1 = 2 * j + 1;
            const float rest = p89[(j >> 1) & 3] * pAB[(j >> 3) & 3];
            const float a0 = (base * p67[k0 & 3]) * rest;
            const float a1 = (base * p67[k1 & 3]) * rest;
            A[j] = pk2(a0, a1);
        }
    }

    // ---------------- 72 lifting gates, fully specialized ----------------
    run_gates<0>(A, &sm, tid, tl6);

    // ---------------- measurement fused with post layer + deferred scale ------
    const float pc = sm.cred[0] * sm.cred[1];   // prod of cos over all gates
    const float s2 = pc * pc;                   // applies quadratically to probs
    float h[NQ];
    meas_h<0>(h, tl6, sm.postw, s2);
    float z = 0.0f;
    meas_packs<0>(z, A, h);
#pragma unroll
    for (int o = 16; o; o >>= 1) z += __shfl_xor_sync(0xffffffffu, z, o);
    if (lane == 0) sm.red[warp] = z;
    __syncthreads();
    if (tid == 0) {
        out[b] = post_b[0] + sm.red[0] + sm.red[1];
    }
}

extern "C" void kernel_launch(void* const* d_in, const int* in_sizes, int n_in,
                              void* d_out, int out_size) {
    const float* x       = (const float*)d_in[0];
    const float* pre_w   = (const float*)d_in[1];
    const float* pre_b   = (const float*)d_in[2];
    const float* weights = (const float*)d_in[3];
    const float* post_w  = (const float*)d_in[4];
    const float* post_b  = (const float*)d_in[5];
    float* out = (float*)d_out;

    int batch = in_sizes[0] / DIN;   // 8192
    dqc_kernel<<<batch, THREADS>>>(x, pre_w, pre_b, weights, post_w, post_b, out);
}